// round 14
// baseline (speedup 1.0000x reference)
#include <cuda_runtime.h>
#include <cuda_fp16.h>
#include <stdint.h>

#define Bsz   4096
#define OBS   1024
#define EOUT  512
#define H1D   2048
#define H2D   2048

// fp16 scratch stored as uint32 half2 words
__device__ uint32_t t_obs[Bsz * OBS / 2];
__device__ uint32_t t_We [EOUT * OBS / 2];
__device__ uint32_t t_dW [OBS * EOUT / 2];
__device__ uint32_t t_W1 [H1D * OBS / 2];
__device__ uint32_t t_W2 [H2D * H1D / 2];
__device__ uint32_t t_e  [Bsz * EOUT / 2];
__device__ uint32_t t_sa [Bsz * OBS / 2];
__device__ uint32_t t_h1 [Bsz * H1D / 2];
__device__ float    g_db [OBS];

__device__ __forceinline__ uint32_t pack_h2(float x, float y) {
    __half2 h = __floats2half2_rn(x, y);
    return *(uint32_t*)&h;
}
__device__ __forceinline__ float tanh_ap(float x) {
    float y;
    asm("tanh.approx.f32 %0, %1;" : "=f"(y) : "f"(x));
    return y;
}
__device__ __forceinline__ float sigmoid_ap(float x) {
    return 0.5f + 0.5f * tanh_ap(0.5f * x);
}
__device__ __forceinline__ uint32_t smem_u32(const void* p) {
    uint32_t a;
    asm("{ .reg .u64 t; cvta.to.shared.u64 t, %1; cvt.u32.u64 %0, t; }"
        : "=r"(a) : "l"(p));
    return a;
}

// ---------------------------------------------------------------------------
// prep_main: convert obs/We to fp16 (critical path)
// ---------------------------------------------------------------------------
__global__ void prep_main(const float* __restrict__ obs, const float* __restrict__ We) {
    const int Q0 = (Bsz * OBS) / 4, Q1 = (EOUT * OBS) / 4;
    const int total = Q0 + Q1;
    int tid0 = blockIdx.x * blockDim.x + threadIdx.x;
    for (int i = tid0; i < total; i += gridDim.x * blockDim.x) {
        int j = i;
        if (j < Q0) {
            float4 v = ((const float4*)obs)[j];
            t_obs[2*j]   = pack_h2(v.x, v.y);
            t_obs[2*j+1] = pack_h2(v.z, v.w);
        } else {
            j -= Q0;
            float4 v = ((const float4*)We)[j];
            t_We[2*j]   = pack_h2(v.x, v.y);
            t_We[2*j+1] = pack_h2(v.z, v.w);
        }
    }
}

// ---------------------------------------------------------------------------
// prep_dw: fold softmax -> sigmoid diff; seed out_v = b3 (side stream)
// ---------------------------------------------------------------------------
__global__ void prep_dw(const float* __restrict__ attn_W,
                        const float* __restrict__ attn_b,
                        const float* __restrict__ b3, float* __restrict__ out_v) {
    const int Q4 = (OBS * EOUT) / 4;
    int tid0 = blockIdx.x * blockDim.x + threadIdx.x;
    for (int j = tid0; j < Q4; j += gridDim.x * blockDim.x) {
        float4 p = ((const float4*)attn_W)[2 * j];
        float4 q = ((const float4*)attn_W)[2 * j + 1];
        t_dW[2*j]   = pack_h2(p.y - p.x, p.w - p.z);
        t_dW[2*j+1] = pack_h2(q.y - q.x, q.w - q.z);
    }
    if (tid0 < OBS) g_db[tid0] = attn_b[2 * tid0 + 1] - attn_b[2 * tid0];
    if (tid0 < Bsz) out_v[tid0] = b3[0];
}

// ---------------------------------------------------------------------------
// prep_heavy: convert W1/W2 (side stream; needed by G4/G5)
// ---------------------------------------------------------------------------
__global__ void prep_heavy(const float* __restrict__ W1, const float* __restrict__ W2) {
    const int Q2 = (H1D * OBS) / 4, Q3 = (H2D * H1D) / 4;
    const int total = Q2 + Q3;
    int tid0 = blockIdx.x * blockDim.x + threadIdx.x;
    for (int i = tid0; i < total; i += gridDim.x * blockDim.x) {
        int j = i;
        if (j < Q2) {
            float4 v = ((const float4*)W1)[j];
            t_W1[2*j]   = pack_h2(v.x, v.y);
            t_W1[2*j+1] = pack_h2(v.z, v.w);
        } else {
            j -= Q2;
            float4 v = ((const float4*)W2)[j];
            t_W2[2*j]   = pack_h2(v.x, v.y);
            t_W2[2*j+1] = pack_h2(v.z, v.w);
        }
    }
}

// ---------------------------------------------------------------------------
// fp16 mma.sync GEMM (m16n8k16), persistent CTAs, cp.async 3-stage pipeline,
// ldmatrix.x4, register double buffering. 128 threads = 2x2 warps.
//   NT  = n-subtiles per warp (8 -> CTA tile 128x128; 4 -> 128x64)
//   OCC = CTAs per SM (2 for NT8 [254 regs]; 3 for NT4 [<=170 regs])
//   stage = A 16KB + B NT*2KB; 3 stages.
// ACT 0: tanh -> fp16 Cv.  ACT 1: sigmoid -> fp32 Cv, C2h = h2(obsH*sig).
// ACT 2: tanh, fused v-reduce: atomicAdd into Cv rows using W3 weights.
// ---------------------------------------------------------------------------
template <int ACT, int NT, int OCC>
__global__ __launch_bounds__(128, OCC)
void mm_fp16(const uint32_t* __restrict__ A, const uint32_t* __restrict__ B,
             const float* __restrict__ bias,
             void* __restrict__ Cv, uint32_t* __restrict__ C2h,
             const uint32_t* __restrict__ obsH, const float* __restrict__ W3,
             int M, int N, int K) {
    extern __shared__ uint32_t sm[];
    const uint32_t SW = 4096u + (uint32_t)NT * 512u;   // stage words
    const int t    = threadIdx.x;
    const int lane = t & 31;
    const int wid  = t >> 5;
    const int wm   = wid & 1;
    const int wn   = wid >> 1;
    const int qr   = lane >> 2;
    const int qc   = lane & 3;
    const int Kw   = K >> 1;

    const int l7 = lane & 7;
    const int g  = lane >> 3;
    const int rowA = (g & 1) << 3;
    const int chA  = g >> 1;
    const int rowB = (g >> 1) << 3;
    const int chB  = g & 1;

    const int r = t >> 3;              // 0..15
    const int q = t & 7;
    const uint32_t smB = smem_u32(sm);
    const uint32_t sw = (uint32_t)((q ^ (r & 7)) << 2);
    const uint32_t aDst0 = (uint32_t)r * 32 + sw;
    const uint32_t bDst0 = 4096u + (uint32_t)r * 32 + sw;
    const int Kw16 = Kw << 4;
    const int NC = K >> 6;

    const int NTILE = NT * 16;         // CTA tile width in n
    const int MT = M >> 7, ntiles = MT * (N / NTILE);

    for (int tile = blockIdx.x; tile < ntiles; tile += gridDim.x) {
        const int m0 = (tile % MT) << 7;
        const int n0 = (tile / MT) * NTILE;

        const uint32_t* aBase = A + (size_t)(m0 + r) * Kw + (q << 2);
        const uint32_t* bBase = B + (size_t)(n0 + r) * Kw + (q << 2);

#define ISSUE_CHUNK(c)                                                        \
    do {                                                                      \
        uint32_t so = (uint32_t)((c) % 3) * SW;                               \
        _Pragma("unroll")                                                     \
        for (int i = 0; i < 8; ++i) {                                         \
            uint32_t da = smB + ((so + aDst0 + (uint32_t)i * 512u) << 2);     \
            asm volatile("cp.async.cg.shared.global [%0], [%1], 16;"          \
                         :: "r"(da), "l"(aBase + i * Kw16 + (c) * 32)         \
                         : "memory");                                         \
        }                                                                     \
        _Pragma("unroll")                                                     \
        for (int i = 0; i < NT; ++i) {                                        \
            uint32_t dbp = smB + ((so + bDst0 + (uint32_t)i * 512u) << 2);    \
            asm volatile("cp.async.cg.shared.global [%0], [%1], 16;"          \
                         :: "r"(dbp), "l"(bBase + i * Kw16 + (c) * 32)        \
                         : "memory");                                         \
        }                                                                     \
        asm volatile("cp.async.commit_group;" ::: "memory");                  \
    } while (0)

#define LDA(ks, mt, buf)                                                      \
    do {                                                                      \
        uint32_t R_ = (uint32_t)(wm * 64 + (mt) * 16 + l7 + rowA);            \
        uint32_t C_ = (uint32_t)(((((ks) << 1) | chA) ^ l7) << 2);            \
        uint32_t ad_ = smB + ((bA + R_ * 32u + C_) << 2);                     \
        asm volatile("ldmatrix.sync.aligned.m8n8.x4.shared.b16 "              \
                     "{%0,%1,%2,%3}, [%4];"                                   \
                     : "=r"(af[buf][0]), "=r"(af[buf][1]),                    \
                       "=r"(af[buf][2]), "=r"(af[buf][3])                     \
                     : "r"(ad_));                                             \
    } while (0)

#define LDB1(ks, p, buf)                                                      \
    do {                                                                      \
        uint32_t R_ = (uint32_t)(wn * (NT * 8) + (p) * 16 + l7 + rowB);       \
        uint32_t C_ = (uint32_t)(((((ks) << 1) | chB) ^ l7) << 2);            \
        uint32_t ad_ = smB + ((bB + R_ * 32u + C_) << 2);                     \
        asm volatile("ldmatrix.sync.aligned.m8n8.x4.shared.b16 "              \
                     "{%0,%1,%2,%3}, [%4];"                                   \
                     : "=r"(bf[buf][2*(p)][0]),   "=r"(bf[buf][2*(p)][1]),    \
                       "=r"(bf[buf][2*(p)+1][0]), "=r"(bf[buf][2*(p)+1][1])   \
                     : "r"(ad_));                                             \
    } while (0)

#define LDB(ks, buf)                                                          \
    do {                                                                      \
        _Pragma("unroll")                                                     \
        for (int p = 0; p < NT / 2; ++p) LDB1(ks, p, buf);                    \
    } while (0)

        float acc[4][NT][4];
#pragma unroll
        for (int i = 0; i < 4; ++i)
#pragma unroll
            for (int j = 0; j < NT; ++j)
#pragma unroll
                for (int k = 0; k < 4; ++k) acc[i][j][k] = 0.0f;

        ISSUE_CHUNK(0);
        ISSUE_CHUNK(1);

        for (int c = 0; c < NC; ++c) {
            if (c + 1 < NC)
                asm volatile("cp.async.wait_group 1;" ::: "memory");
            else
                asm volatile("cp.async.wait_group 0;" ::: "memory");
            __syncthreads();

            const uint32_t bA = (uint32_t)(c % 3) * SW;
            const uint32_t bB = bA + 4096u;

            uint32_t bf[2][NT][2];
            uint32_t af[2][4];

            LDB(0, 0);
            LDA(0, 0, 0);
            if (c + 2 < NC) ISSUE_CHUNK(c + 2);

#pragma unroll
            for (int ks = 0; ks < 4; ++ks) {
                if (ks < 3) LDB(ks + 1, (ks + 1) & 1);
#pragma unroll
                for (int mt = 0; mt < 4; ++mt) {
                    if (mt < 3)      LDA(ks, mt + 1, (mt + 1) & 1);
                    else if (ks < 3) LDA(ks + 1, 0, 0);
                    const uint32_t* a = af[mt & 1];
#pragma unroll
                    for (int nt = 0; nt < NT; ++nt) {
                        asm volatile(
                            "mma.sync.aligned.m16n8k16.row.col.f32.f16.f16.f32 "
                            "{%0,%1,%2,%3}, {%4,%5,%6,%7}, {%8,%9}, {%0,%1,%2,%3};"
                            : "+f"(acc[mt][nt][0]), "+f"(acc[mt][nt][1]),
                              "+f"(acc[mt][nt][2]), "+f"(acc[mt][nt][3])
                            : "r"(a[0]), "r"(a[1]), "r"(a[2]), "r"(a[3]),
                              "r"(bf[ks & 1][nt][0]), "r"(bf[ks & 1][nt][1]));
                    }
                }
            }
        }
#undef ISSUE_CHUNK
#undef LDA
#undef LDB1
#undef LDB

        // epilogue
        const int Nw = N >> 1;
#pragma unroll
        for (int mt = 0; mt < 4; ++mt) {
            const int m = m0 + wm * 64 + mt * 16 + qr;
            float vsum[2] = {0.0f, 0.0f};
#pragma unroll
            for (int nt = 0; nt < NT; ++nt) {
                const int n = n0 + wn * (NT * 8) + nt * 8 + 2 * qc;
                const float bx = bias[n], by = bias[n + 1];
#pragma unroll
                for (int h = 0; h < 2; ++h) {
                    const int mm = m + 8 * h;
                    float vx = acc[mt][nt][2 * h + 0] + bx;
                    float vy = acc[mt][nt][2 * h + 1] + by;
                    if (ACT == 0) {
                        vx = tanh_ap(vx); vy = tanh_ap(vy);
                        ((uint32_t*)Cv)[(size_t)mm * Nw + (n >> 1)] = pack_h2(vx, vy);
                    } else if (ACT == 1) {
                        vx = sigmoid_ap(vx); vy = sigmoid_ap(vy);
                        *(float2*)((float*)Cv + (size_t)mm * N + n) = make_float2(vx, vy);
                        __half2 oh = *(const __half2*)&obsH[(size_t)mm * Nw + (n >> 1)];
                        float2 ob = __half22float2(oh);
                        C2h[(size_t)mm * Nw + (n >> 1)] = pack_h2(ob.x * vx, ob.y * vy);
                    } else {
                        vx = tanh_ap(vx); vy = tanh_ap(vy);
                        vsum[h] += vx * W3[n] + vy * W3[n + 1];
                    }
                }
            }
            if (ACT == 2) {
#pragma unroll
                for (int h = 0; h < 2; ++h) {
                    float s = vsum[h];
                    s += __shfl_xor_sync(0xffffffffu, s, 1);
                    s += __shfl_xor_sync(0xffffffffu, s, 2);
                    if (qc == 0)
                        atomicAdd((float*)Cv + (m + 8 * h), s);
                }
            }
        }
        __syncthreads();
    }
}

// ---------------------------------------------------------------------------
// Launch
// ---------------------------------------------------------------------------
extern "C" void kernel_launch(void* const* d_in, const int* in_sizes, int n_in,
                              void* d_out, int out_size) {
    const float* obs    = (const float*)d_in[0];
    const float* We     = (const float*)d_in[1];
    const float* be     = (const float*)d_in[2];
    const float* attn_W = (const float*)d_in[3];
    const float* attn_b = (const float*)d_in[4];
    const float* W1     = (const float*)d_in[5];
    const float* b1     = (const float*)d_in[6];
    const float* W2     = (const float*)d_in[7];
    const float* b2     = (const float*)d_in[8];
    const float* W3     = (const float*)d_in[9];
    const float* b3     = (const float*)d_in[10];

    float* out_v    = (float*)d_out;
    float* out_attn = (float*)d_out + Bsz;

    uint32_t *pobs, *pWe, *pdW, *pW1, *pW2, *pe, *psa, *ph1;
    float* pdb;
    cudaGetSymbolAddress((void**)&pobs, t_obs);
    cudaGetSymbolAddress((void**)&pWe,  t_We);
    cudaGetSymbolAddress((void**)&pdW,  t_dW);
    cudaGetSymbolAddress((void**)&pW1,  t_W1);
    cudaGetSymbolAddress((void**)&pW2,  t_W2);
    cudaGetSymbolAddress((void**)&pe,   t_e);
    cudaGetSymbolAddress((void**)&psa,  t_sa);
    cudaGetSymbolAddress((void**)&ph1,  t_h1);
    cudaGetSymbolAddress((void**)&pdb,  g_db);

    const int SMEM8 = 3 * 8192 * 4;   // 96 KB (NT=8)
    const int SMEM4 = 3 * 6144 * 4;   // 72 KB (NT=4)
    cudaFuncSetAttribute(mm_fp16<0, 4, 2>, cudaFuncAttributeMaxDynamicSharedMemorySize, SMEM4);
    cudaFuncSetAttribute(mm_fp16<1, 8, 2>, cudaFuncAttributeMaxDynamicSharedMemorySize, SMEM8);
    cudaFuncSetAttribute(mm_fp16<0, 4, 3>, cudaFuncAttributeMaxDynamicSharedMemorySize, SMEM4);
    cudaFuncSetAttribute(mm_fp16<2, 4, 3>, cudaFuncAttributeMaxDynamicSharedMemorySize, SMEM4);

    const int PGRID2 = 2 * 148;       // 2 CTAs/SM
    const int PGRID3 = 3 * 148;       // 3 CTAs/SM

    // side stream: dW + out_v seed (needed by G3/G5), then W1/W2 (G4/G5)
    cudaStream_t sHeavy;
    cudaStreamCreateWithFlags(&sHeavy, cudaStreamNonBlocking);
    cudaEvent_t evFork, evA, evB;
    cudaEventCreateWithFlags(&evFork, cudaEventDisableTiming);
    cudaEventCreateWithFlags(&evA, cudaEventDisableTiming);
    cudaEventCreateWithFlags(&evB, cudaEventDisableTiming);

    cudaEventRecord(evFork, 0);
    cudaStreamWaitEvent(sHeavy, evFork, 0);
    prep_dw<<<512, 256, 0, sHeavy>>>(attn_W, attn_b, b3, out_v);
    cudaEventRecord(evA, sHeavy);
    prep_heavy<<<1480, 256, 0, sHeavy>>>(W1, W2);
    cudaEventRecord(evB, sHeavy);

    // main: obs/We conversion (critical), then GEMM chain
    prep_main<<<1024, 256>>>(obs, We);

    // G2: e = tanh(obs @ We^T + be)   [NT=4 -> 256 tiles, 1 wave]
    mm_fp16<0, 4, 2><<<PGRID2, 128, SMEM4>>>(pobs, pWe, be, pe, nullptr,
                                             nullptr, nullptr, Bsz, EOUT, OBS);

    cudaStreamWaitEvent(0, evA, 0);
    // G3: att = sigmoid(e @ dW^T + db); sa = h2(obs*att)
    mm_fp16<1, 8, 2><<<PGRID2, 128, SMEM8>>>(pe, pdW, pdb, out_attn, psa,
                                             pobs, nullptr, Bsz, OBS, EOUT);

    cudaStreamWaitEvent(0, evB, 0);
    // G4: h1 = tanh(sa @ W1^T + b1)   [NT=4, 3 CTA/SM, 1024 tiles]
    mm_fp16<0, 4, 3><<<PGRID3, 128, SMEM4>>>(psa, pW1, b1, ph1, nullptr,
                                             nullptr, nullptr, Bsz, H1D, OBS);

    // G5: v += rowsum(tanh(h1 @ W2^T + b2) * W3)   [NT=4, 3 CTA/SM]
    mm_fp16<2, 4, 3><<<PGRID3, 128, SMEM4>>>(ph1, pW2, b2, out_v, nullptr,
                                             nullptr, W3, Bsz, H2D, H1D);
}

// round 15
// speedup vs baseline: 1.1037x; 1.1037x over previous
#include <cuda_runtime.h>
#include <cuda_fp16.h>
#include <stdint.h>

#define Bsz   4096
#define OBS   1024
#define EOUT  512
#define H1D   2048
#define H2D   2048

// fp16 scratch stored as uint32 half2 words
__device__ uint32_t t_obs[Bsz * OBS / 2];
__device__ uint32_t t_We [EOUT * OBS / 2];
__device__ uint32_t t_dW [OBS * EOUT / 2];
__device__ uint32_t t_W1 [H1D * OBS / 2];
__device__ uint32_t t_W2 [H2D * H1D / 2];
__device__ uint32_t t_e  [Bsz * EOUT / 2];
__device__ uint32_t t_sa [Bsz * OBS / 2];
__device__ uint32_t t_h1 [Bsz * H1D / 2];
__device__ float    g_db [OBS];
__device__ int      g_sync[128];   // [0..31]=g2 rows, [64..95]=g4 rows

#define PGRID 296

__device__ __forceinline__ uint32_t pack_h2(float x, float y) {
    __half2 h = __floats2half2_rn(x, y);
    return *(uint32_t*)&h;
}
__device__ __forceinline__ float tanh_ap(float x) {
    float y;
    asm("tanh.approx.f32 %0, %1;" : "=f"(y) : "f"(x));
    return y;
}
__device__ __forceinline__ float sigmoid_ap(float x) {
    return 0.5f + 0.5f * tanh_ap(0.5f * x);
}
__device__ __forceinline__ uint32_t smem_u32(const void* p) {
    uint32_t a;
    asm("{ .reg .u64 t; cvta.to.shared.u64 t, %1; cvt.u32.u64 %0, t; }"
        : "=r"(a) : "l"(p));
    return a;
}
__device__ __forceinline__ void spin_ge(const int* p, int need) {
    int v;
    asm volatile("ld.acquire.gpu.global.b32 %0, [%1];" : "=r"(v) : "l"(p) : "memory");
    while (v < need) {
        __nanosleep(128);
        asm volatile("ld.acquire.gpu.global.b32 %0, [%1];" : "=r"(v) : "l"(p) : "memory");
    }
}
__device__ __forceinline__ void sig_add(int* p) {
    asm volatile("red.release.gpu.global.add.s32 [%0], 1;" :: "l"(p) : "memory");
}

// ---------------------------------------------------------------------------
// prep_main: convert obs/We to fp16 (critical path)
// ---------------------------------------------------------------------------
__global__ void prep_main(const float* __restrict__ obs, const float* __restrict__ We) {
    const int Q0 = (Bsz * OBS) / 4, Q1 = (EOUT * OBS) / 4;
    const int total = Q0 + Q1;
    int tid0 = blockIdx.x * blockDim.x + threadIdx.x;
    for (int i = tid0; i < total; i += gridDim.x * blockDim.x) {
        int j = i;
        if (j < Q0) {
            float4 v = ((const float4*)obs)[j];
            t_obs[2*j]   = pack_h2(v.x, v.y);
            t_obs[2*j+1] = pack_h2(v.z, v.w);
        } else {
            j -= Q0;
            float4 v = ((const float4*)We)[j];
            t_We[2*j]   = pack_h2(v.x, v.y);
            t_We[2*j+1] = pack_h2(v.z, v.w);
        }
    }
}

// ---------------------------------------------------------------------------
// prep_dw: fold softmax; zero sync counters; seed out_v = b3 (side stream)
// ---------------------------------------------------------------------------
__global__ void prep_dw(const float* __restrict__ attn_W,
                        const float* __restrict__ attn_b,
                        const float* __restrict__ b3, float* __restrict__ out_v) {
    const int Q4 = (OBS * EOUT) / 4;
    int tid0 = blockIdx.x * blockDim.x + threadIdx.x;
    for (int j = tid0; j < Q4; j += gridDim.x * blockDim.x) {
        float4 p = ((const float4*)attn_W)[2 * j];
        float4 q = ((const float4*)attn_W)[2 * j + 1];
        t_dW[2*j]   = pack_h2(p.y - p.x, p.w - p.z);
        t_dW[2*j+1] = pack_h2(q.y - q.x, q.w - q.z);
    }
    if (tid0 < OBS) g_db[tid0] = attn_b[2 * tid0 + 1] - attn_b[2 * tid0];
    if (tid0 < 128) g_sync[tid0] = 0;
    if (tid0 < Bsz) out_v[tid0] = b3[0];
}

// ---------------------------------------------------------------------------
// prep_heavy: convert W1/W2 (side stream; needed by G4/G5)
// ---------------------------------------------------------------------------
__global__ void prep_heavy(const float* __restrict__ W1, const float* __restrict__ W2) {
    const int Q2 = (H1D * OBS) / 4, Q3 = (H2D * H1D) / 4;
    const int total = Q2 + Q3;
    int tid0 = blockIdx.x * blockDim.x + threadIdx.x;
    for (int i = tid0; i < total; i += gridDim.x * blockDim.x) {
        int j = i;
        if (j < Q2) {
            float4 v = ((const float4*)W1)[j];
            t_W1[2*j]   = pack_h2(v.x, v.y);
            t_W1[2*j+1] = pack_h2(v.z, v.w);
        } else {
            j -= Q2;
            float4 v = ((const float4*)W2)[j];
            t_W2[2*j]   = pack_h2(v.x, v.y);
            t_W2[2*j+1] = pack_h2(v.z, v.w);
        }
    }
}

// ---------------------------------------------------------------------------
// one 128x128 GEMM tile (proven core): fp16 m16n8k16, cp.async 3-stage,
// ldmatrix.x4, register double buffering. 128 threads = 2x2 warps, 64x64/warp.
// ACT 0: tanh -> fp16 Cv.  ACT 1: sigmoid -> fp32 Cv, C2h = h2(obsH*sig).
// ACT 2: tanh, fused v-reduce: atomicAdd into Cv rows using W3 weights.
// ---------------------------------------------------------------------------
template <int ACT>
__device__ __forceinline__ void gemm_tile(
        const uint32_t* __restrict__ A, const uint32_t* __restrict__ B,
        const float* __restrict__ bias, void* __restrict__ Cv,
        uint32_t* __restrict__ C2h, const uint32_t* __restrict__ obsH,
        const float* __restrict__ W3,
        int N, int K, int m0, int n0, uint32_t* sm) {
    const int t    = threadIdx.x;
    const int lane = t & 31;
    const int wid  = t >> 5;
    const int wm   = wid & 1;
    const int wn   = wid >> 1;
    const int qr   = lane >> 2;
    const int qc   = lane & 3;
    const int Kw   = K >> 1;

    const int l7 = lane & 7;
    const int g  = lane >> 3;
    const int rowA = (g & 1) << 3;
    const int chA  = g >> 1;
    const int rowB = (g >> 1) << 3;
    const int chB  = g & 1;

    const int r = t >> 3;
    const int q = t & 7;
    const uint32_t smB = smem_u32(sm);
    const uint32_t sw = (uint32_t)((q ^ (r & 7)) << 2);
    const uint32_t aDst0 = (uint32_t)r * 32 + sw;
    const uint32_t bDst0 = 4096u + (uint32_t)r * 32 + sw;
    const int Kw16 = Kw << 4;
    const int NC = K >> 6;

    const uint32_t* aBase = A + (size_t)(m0 + r) * Kw + (q << 2);
    const uint32_t* bBase = B + (size_t)(n0 + r) * Kw + (q << 2);

#define ISSUE_CHUNK(c)                                                        \
    do {                                                                      \
        uint32_t so = (uint32_t)((c) % 3) * 8192u;                            \
        _Pragma("unroll")                                                     \
        for (int i = 0; i < 8; ++i) {                                         \
            uint32_t da = smB + ((so + aDst0 + (uint32_t)i * 512u) << 2);     \
            asm volatile("cp.async.cg.shared.global [%0], [%1], 16;"          \
                         :: "r"(da), "l"(aBase + i * Kw16 + (c) * 32)         \
                         : "memory");                                         \
        }                                                                     \
        _Pragma("unroll")                                                     \
        for (int i = 0; i < 8; ++i) {                                         \
            uint32_t dbp = smB + ((so + bDst0 + (uint32_t)i * 512u) << 2);    \
            asm volatile("cp.async.cg.shared.global [%0], [%1], 16;"          \
                         :: "r"(dbp), "l"(bBase + i * Kw16 + (c) * 32)        \
                         : "memory");                                         \
        }                                                                     \
        asm volatile("cp.async.commit_group;" ::: "memory");                  \
    } while (0)

#define LDA(ks, mt, buf)                                                      \
    do {                                                                      \
        uint32_t R_ = (uint32_t)(wm * 64 + (mt) * 16 + l7 + rowA);            \
        uint32_t C_ = (uint32_t)(((((ks) << 1) | chA) ^ l7) << 2);            \
        uint32_t ad_ = smB + ((bA + R_ * 32u + C_) << 2);                     \
        asm volatile("ldmatrix.sync.aligned.m8n8.x4.shared.b16 "              \
                     "{%0,%1,%2,%3}, [%4];"                                   \
                     : "=r"(af[buf][0]), "=r"(af[buf][1]),                    \
                       "=r"(af[buf][2]), "=r"(af[buf][3])                     \
                     : "r"(ad_));                                             \
    } while (0)

#define LDB1(ks, p, buf)                                                      \
    do {                                                                      \
        uint32_t R_ = (uint32_t)(wn * 64 + (p) * 16 + l7 + rowB);             \
        uint32_t C_ = (uint32_t)(((((ks) << 1) | chB) ^ l7) << 2);            \
        uint32_t ad_ = smB + ((bB + R_ * 32u + C_) << 2);                     \
        asm volatile("ldmatrix.sync.aligned.m8n8.x4.shared.b16 "              \
                     "{%0,%1,%2,%3}, [%4];"                                   \
                     : "=r"(bf[buf][2*(p)][0]),   "=r"(bf[buf][2*(p)][1]),    \
                       "=r"(bf[buf][2*(p)+1][0]), "=r"(bf[buf][2*(p)+1][1])   \
                     : "r"(ad_));                                             \
    } while (0)

#define LDB(ks, buf) \
    do { LDB1(ks, 0, buf); LDB1(ks, 1, buf); LDB1(ks, 2, buf); LDB1(ks, 3, buf); } while (0)

    float acc[4][8][4];
#pragma unroll
    for (int i = 0; i < 4; ++i)
#pragma unroll
        for (int j = 0; j < 8; ++j)
#pragma unroll
            for (int k = 0; k < 4; ++k) acc[i][j][k] = 0.0f;

    ISSUE_CHUNK(0);
    ISSUE_CHUNK(1);

    for (int c = 0; c < NC; ++c) {
        if (c + 1 < NC)
            asm volatile("cp.async.wait_group 1;" ::: "memory");
        else
            asm volatile("cp.async.wait_group 0;" ::: "memory");
        __syncthreads();

        const uint32_t bA = (uint32_t)(c % 3) * 8192u;
        const uint32_t bB = bA + 4096u;

        uint32_t bf[2][8][2];
        uint32_t af[2][4];

        LDB(0, 0);
        LDA(0, 0, 0);
        if (c + 2 < NC) ISSUE_CHUNK(c + 2);

#pragma unroll
        for (int ks = 0; ks < 4; ++ks) {
            if (ks < 3) LDB(ks + 1, (ks + 1) & 1);
#pragma unroll
            for (int mt = 0; mt < 4; ++mt) {
                if (mt < 3)      LDA(ks, mt + 1, (mt + 1) & 1);
                else if (ks < 3) LDA(ks + 1, 0, 0);
                const uint32_t* a = af[mt & 1];
#pragma unroll
                for (int nt = 0; nt < 8; ++nt) {
                    asm volatile(
                        "mma.sync.aligned.m16n8k16.row.col.f32.f16.f16.f32 "
                        "{%0,%1,%2,%3}, {%4,%5,%6,%7}, {%8,%9}, {%0,%1,%2,%3};"
                        : "+f"(acc[mt][nt][0]), "+f"(acc[mt][nt][1]),
                          "+f"(acc[mt][nt][2]), "+f"(acc[mt][nt][3])
                        : "r"(a[0]), "r"(a[1]), "r"(a[2]), "r"(a[3]),
                          "r"(bf[ks & 1][nt][0]), "r"(bf[ks & 1][nt][1]));
                }
            }
        }
    }
#undef ISSUE_CHUNK
#undef LDA
#undef LDB1
#undef LDB

    const int Nw = N >> 1;
#pragma unroll
    for (int mt = 0; mt < 4; ++mt) {
        const int m = m0 + wm * 64 + mt * 16 + qr;
        float vsum[2] = {0.0f, 0.0f};
#pragma unroll
        for (int nt = 0; nt < 8; ++nt) {
            const int n = n0 + wn * 64 + nt * 8 + 2 * qc;
            const float bx = bias[n], by = bias[n + 1];
#pragma unroll
            for (int h = 0; h < 2; ++h) {
                const int mm = m + 8 * h;
                float vx = acc[mt][nt][2 * h + 0] + bx;
                float vy = acc[mt][nt][2 * h + 1] + by;
                if (ACT == 0) {
                    vx = tanh_ap(vx); vy = tanh_ap(vy);
                    ((uint32_t*)Cv)[(size_t)mm * Nw + (n >> 1)] = pack_h2(vx, vy);
                } else if (ACT == 1) {
                    vx = sigmoid_ap(vx); vy = sigmoid_ap(vy);
                    *(float2*)((float*)Cv + (size_t)mm * N + n) = make_float2(vx, vy);
                    __half2 oh = *(const __half2*)&obsH[(size_t)mm * Nw + (n >> 1)];
                    float2 ob = __half22float2(oh);
                    C2h[(size_t)mm * Nw + (n >> 1)] = pack_h2(ob.x * vx, ob.y * vy);
                } else {
                    vx = tanh_ap(vx); vy = tanh_ap(vy);
                    vsum[h] += vx * W3[n] + vy * W3[n + 1];
                }
            }
        }
        if (ACT == 2) {
#pragma unroll
            for (int h = 0; h < 2; ++h) {
                float s = vsum[h];
                s += __shfl_xor_sync(0xffffffffu, s, 1);
                s += __shfl_xor_sync(0xffffffffu, s, 2);
                if (qc == 0)
                    atomicAdd((float*)Cv + (m + 8 * h), s);
            }
        }
    }
}

// ---------------------------------------------------------------------------
// g23: G2 (128 tiles, row-major) then G3 (256 tiles, spin on g2 row)
// ---------------------------------------------------------------------------
__global__ __launch_bounds__(128, 2)
void g23_fused(const float* __restrict__ be, float* __restrict__ out_attn) {
    extern __shared__ uint32_t sm[];
    const int t = threadIdx.x;
    for (int T = blockIdx.x; T < 384; T += PGRID) {
        if (T < 128) {
            // G2: e = tanh(obs @ We^T + be); row mr = T>>2
            int mr = T >> 2, n0 = (T & 3) << 7;
            gemm_tile<0>(t_obs, t_We, be, t_e, nullptr, nullptr, nullptr,
                         EOUT, OBS, mr << 7, n0, sm);
            __syncthreads();
            if (t == 0) sig_add(&g_sync[mr]);
        } else {
            // G3: att = sigmoid(e @ dW^T + db); sa = h2(obs*att)
            int tt = T - 128;
            int mr = tt >> 3, n0 = (tt & 7) << 7;
            if (t == 0) spin_ge(&g_sync[mr], 4);
            __syncthreads();
            gemm_tile<1>(t_e, t_dW, g_db, out_attn, t_sa, t_obs, nullptr,
                         OBS, EOUT, mr << 7, n0, sm);
            __syncthreads();
        }
    }
}

// ---------------------------------------------------------------------------
// g45: G4 (512 tiles, row-major) then G5 (512 tiles, spin on g4 row)
// ---------------------------------------------------------------------------
__global__ __launch_bounds__(128, 2)
void g45_fused(const float* __restrict__ b1, const float* __restrict__ b2,
               const float* __restrict__ W3, float* __restrict__ out_v) {
    extern __shared__ uint32_t sm[];
    const int t = threadIdx.x;
    for (int T = blockIdx.x; T < 1024; T += PGRID) {
        if (T < 512) {
            // G4: h1 = tanh(sa @ W1^T + b1); row mr = T>>4
            int mr = T >> 4, n0 = (T & 15) << 7;
            gemm_tile<0>(t_sa, t_W1, b1, t_h1, nullptr, nullptr, nullptr,
                         H1D, OBS, mr << 7, n0, sm);
            __syncthreads();
            if (t == 0) sig_add(&g_sync[64 + mr]);
        } else {
            // G5: v += rowsum(tanh(h1 @ W2^T + b2) * W3)
            int tt = T - 512;
            int mr = tt >> 4, n0 = (tt & 15) << 7;
            if (t == 0) spin_ge(&g_sync[64 + mr], 16);
            __syncthreads();
            gemm_tile<2>(t_h1, t_W2, b2, out_v, nullptr, nullptr, W3,
                         H2D, H1D, mr << 7, n0, sm);
            __syncthreads();
        }
    }
}

// ---------------------------------------------------------------------------
// Launch
// ---------------------------------------------------------------------------
extern "C" void kernel_launch(void* const* d_in, const int* in_sizes, int n_in,
                              void* d_out, int out_size) {
    const float* obs    = (const float*)d_in[0];
    const float* We     = (const float*)d_in[1];
    const float* be     = (const float*)d_in[2];
    const float* attn_W = (const float*)d_in[3];
    const float* attn_b = (const float*)d_in[4];
    const float* W1     = (const float*)d_in[5];
    const float* b1     = (const float*)d_in[6];
    const float* W2     = (const float*)d_in[7];
    const float* b2     = (const float*)d_in[8];
    const float* W3     = (const float*)d_in[9];
    const float* b3     = (const float*)d_in[10];

    float* out_v    = (float*)d_out;
    float* out_attn = (float*)d_out + Bsz;

    const int SMEM = 3 * 8192 * 4;   // 96 KB
    cudaFuncSetAttribute(g23_fused, cudaFuncAttributeMaxDynamicSharedMemorySize, SMEM);
    cudaFuncSetAttribute(g45_fused, cudaFuncAttributeMaxDynamicSharedMemorySize, SMEM);

    // side stream: dW + counters + out_v seed (before g23), then W1/W2 (before g45)
    cudaStream_t sHeavy;
    cudaStreamCreateWithFlags(&sHeavy, cudaStreamNonBlocking);
    cudaEvent_t evFork, evA, evB;
    cudaEventCreateWithFlags(&evFork, cudaEventDisableTiming);
    cudaEventCreateWithFlags(&evA, cudaEventDisableTiming);
    cudaEventCreateWithFlags(&evB, cudaEventDisableTiming);

    cudaEventRecord(evFork, 0);
    cudaStreamWaitEvent(sHeavy, evFork, 0);
    prep_dw<<<512, 256, 0, sHeavy>>>(attn_W, attn_b, b3, out_v);
    cudaEventRecord(evA, sHeavy);
    prep_heavy<<<1480, 256, 0, sHeavy>>>(W1, W2);
    cudaEventRecord(evB, sHeavy);

    // main: obs/We conversion (critical), then two fused GEMM pairs
    prep_main<<<1024, 256>>>(obs, We);

    cudaStreamWaitEvent(0, evA, 0);
    g23_fused<<<PGRID, 128, SMEM>>>(be, out_attn);

    cudaStreamWaitEvent(0, evB, 0);
    g45_fused<<<PGRID, 128, SMEM>>>(b1, b2, W3, out_v);
}